// round 12
// baseline (speedup 1.0000x reference)
#include <cuda_runtime.h>
#include <cuda_bf16.h>
#include <cstdint>

#define N_EMBED 384
#define NUM_EXPERTS 8
#define THREADS 128
#define TPT 2
#define TOK_PER_BLK (THREADS * TPT)   // 256
#define KC 24                         // dims per chunk
#define NCHUNK (N_EMBED / KC)         // 16
#define NBUF 3
#define PITCH 28                      // floats per token row; (7t mod 8) distinct -> conflict-free .128

#define WS_BYTES (NUM_EXPERTS * N_EMBED * 8)          // 24576
#define XS_OFF   (WS_BYTES + 64)                      // 24640 (sb in gap)
#define XS_BUF_FLOATS (TOK_PER_BLK * PITCH)           // 7168 floats = 28672 B
#define SMEM_TOTAL (XS_OFF + NBUF * XS_BUF_FLOATS * 4)  // 110656 B -> 2 CTAs/SM

#define CP_PER_CHUNK (TOK_PER_BLK * (KC / 4) / THREADS)  // 12 float4 per thread

typedef unsigned long long ull;

__device__ __forceinline__ void ffma2(ull& a, ull b, ull c) {
    asm("fma.rn.f32x2 %0, %1, %2, %0;" : "+l"(a) : "l"(b), "l"(c));
}
__device__ __forceinline__ ull bcast2(float v) {
    ull r; asm("mov.b64 %0, {%1, %1};" : "=l"(r) : "f"(v)); return r;
}
__device__ __forceinline__ ull pack2(float lo, float hi) {
    ull r; asm("mov.b64 %0, {%1, %2};" : "=l"(r) : "f"(lo), "f"(hi)); return r;
}
__device__ __forceinline__ void unpack2(ull a, float& lo, float& hi) {
    asm("mov.b64 {%0, %1}, %2;" : "=f"(lo), "=f"(hi) : "l"(a));
}
__device__ __forceinline__ uint32_t smem_u32(const void* p) {
    return (uint32_t)__cvta_generic_to_shared(p);
}
__device__ __forceinline__ void cp16(uint32_t dst, const void* src, int pred) {
    asm volatile(
        "{ .reg .pred q; setp.ne.b32 q, %2, 0;\n\t"
        "@q cp.async.ca.shared.global [%0], [%1], 16; }"
        :: "r"(dst), "l"(src), "r"(pred));
}

__global__ __launch_bounds__(THREADS, 2)
void noisy_topk_router_kernel(
    const float* __restrict__ x,        // [n_tok, 384]
    const float* __restrict__ noise,    // [n_tok, 8]
    const float* __restrict__ w_route,  // [8, 384]
    const float* __restrict__ b_route,  // [8]
    const float* __restrict__ w_noise,  // [8, 384]
    const float* __restrict__ b_noise,  // [8]
    float* __restrict__ out,
    int n_tok, int write_idx)
{
    extern __shared__ char smem[];
    float2* ws = reinterpret_cast<float2*>(smem);            // (route, noise) per [e][d]
    float*  sb = reinterpret_cast<float*>(smem + WS_BYTES);  // 16 biases
    float*  xs = reinterpret_cast<float*>(smem + XS_OFF);    // [3][256*28]

    const int tid = threadIdx.x;
    const int t0  = blockIdx.x * TOK_PER_BLK;

    // ---- async staging of x chunk c: 256 tokens x 24 floats (6 float4/row) ----
    auto stage = [&](int c) {
        float* dst = xs + (c % NBUF) * XS_BUF_FLOATS;
#pragma unroll
        for (int r = 0; r < CP_PER_CHUNK; r++) {             // 12
            int idx = tid + r * THREADS;                     // 0..1535
            int tok = idx / 6, q = idx % 6;
            const float* src = x + (size_t)(t0 + tok) * N_EMBED + c * KC + q * 4;
            cp16(smem_u32(dst + tok * PITCH + q * 4), src, (t0 + tok < n_tok) ? 1 : 0);
        }
        asm volatile("cp.async.commit_group;" ::: "memory");
    };

    // depth-3 prologue: 2 chunks of prefetch distance
    stage(0);
    stage(1);
    stage(2);

    // weights + biases into smem while prefetch flies
    for (int i = tid; i < NUM_EXPERTS * N_EMBED; i += THREADS)
        ws[i] = make_float2(w_route[i], w_noise[i]);
    if (tid < NUM_EXPERTS)           sb[tid] = b_route[tid];
    else if (tid < 2 * NUM_EXPERTS)  sb[tid] = b_noise[tid - NUM_EXPERTS];

    // noise prefetch for this thread's 2 tokens
    float4 nzr[TPT][2];
#pragma unroll
    for (int k = 0; k < TPT; k++) {
        int t = t0 + tid + k * THREADS;
        if (t < n_tok) {
            const float4* np = reinterpret_cast<const float4*>(noise + (size_t)t * NUM_EXPERTS);
            nzr[k][0] = np[0]; nzr[k][1] = np[1];
        } else {
            nzr[k][0] = nzr[k][1] = make_float4(0.f, 0.f, 0.f, 0.f);
        }
    }

    asm volatile("cp.async.wait_group 2;" ::: "memory");   // chunk 0 landed (this thread)
    __syncthreads();                                       // everyone's chunk 0 + ws + sb visible

    ull acc[TPT][NUM_EXPERTS];
#pragma unroll
    for (int k = 0; k < TPT; k++)
#pragma unroll
        for (int e = 0; e < NUM_EXPERTS; e++)
            acc[k][e] = pack2(sb[e], sb[NUM_EXPERTS + e]);

    const float* wsf = reinterpret_cast<const float*>(ws);

    for (int c = 0; c < NCHUNK; c++) {
        const float* buf = xs + (c % NBUF) * XS_BUF_FLOATS;
#pragma unroll
        for (int j = 0; j < KC; j += 4) {
            ull xb[TPT][4];
#pragma unroll
            for (int k = 0; k < TPT; k++) {
                float4 xv = *reinterpret_cast<const float4*>(&buf[(tid + k * THREADS) * PITCH + j]);
                xb[k][0] = bcast2(xv.x); xb[k][1] = bcast2(xv.y);
                xb[k][2] = bcast2(xv.z); xb[k][3] = bcast2(xv.w);
            }
            const int d = c * KC + j;
#pragma unroll
            for (int e = 0; e < NUM_EXPERTS; e++) {
                const float* wpe = wsf + (e * N_EMBED + d) * 2;
                ulonglong2 wa = *reinterpret_cast<const ulonglong2*>(wpe);      // d, d+1
                ulonglong2 wb = *reinterpret_cast<const ulonglong2*>(wpe + 4);  // d+2, d+3
#pragma unroll
                for (int k = 0; k < TPT; k++) {
                    ffma2(acc[k][e], xb[k][0], wa.x);
                    ffma2(acc[k][e], xb[k][1], wa.y);
                    ffma2(acc[k][e], xb[k][2], wb.x);
                    ffma2(acc[k][e], xb[k][3], wb.y);
                }
            }
        }
        __syncthreads();                       // all readers of buf (c%3) done
        if (c + 3 < NCHUNK) stage(c + 3);      // refill slot just freed
        else asm volatile("cp.async.commit_group;" ::: "memory");
        asm volatile("cp.async.wait_group 2;" ::: "memory");   // chunk c+1 landed (this thread)
        __syncthreads();                       // chunk c+1 visible to all
    }

    // ---- epilogue per token ----
#pragma unroll
    for (int k = 0; k < TPT; k++) {
        int t = t0 + tid + k * THREADS;
        if (t >= n_tok) continue;

        float nz[NUM_EXPERTS] = {nzr[k][0].x, nzr[k][0].y, nzr[k][0].z, nzr[k][0].w,
                                 nzr[k][1].x, nzr[k][1].y, nzr[k][1].z, nzr[k][1].w};

        float v[NUM_EXPERTS];
#pragma unroll
        for (int e = 0; e < NUM_EXPERTS; e++) {
            float lg, nl;
            unpack2(acc[k][e], lg, nl);
            // jax.nn.softplus: max(x,0) + log1p(exp(-|x|))
            float sp = fmaxf(nl, 0.0f) + log1pf(expf(-fabsf(nl)));
            v[e] = lg + nz[e] * sp;
        }

        // top-2, first-occurrence tie-break (matches jax.lax.top_k)
        float v0 = v[0]; int i0 = 0;
#pragma unroll
        for (int e = 1; e < NUM_EXPERTS; e++)
            if (v[e] > v0) { v0 = v[e]; i0 = e; }
        float v1 = -3.402823466e+38f; int i1 = 0;
#pragma unroll
        for (int e = 0; e < NUM_EXPERTS; e++) {
            bool take = (e != i0) && (v[e] > v1);
            if (take) { v1 = v[e]; i1 = e; }
        }

        float e1 = expf(v1 - v0);
        float inv = 1.0f / (1.0f + e1);
        float p0 = inv, p1 = e1 * inv;

        float o[NUM_EXPERTS];
#pragma unroll
        for (int e = 0; e < NUM_EXPERTS; e++)
            o[e] = (e == i0) ? p0 : ((e == i1) ? p1 : 0.0f);

        float4* op = reinterpret_cast<float4*>(out + (size_t)t * NUM_EXPERTS);
        op[0] = make_float4(o[0], o[1], o[2], o[3]);
        op[1] = make_float4(o[4], o[5], o[6], o[7]);

        if (write_idx) {
            float2* ip = reinterpret_cast<float2*>(out + (size_t)n_tok * NUM_EXPERTS);
            ip[t] = make_float2((float)i0, (float)i1);
        }
    }
}

extern "C" void kernel_launch(void* const* d_in, const int* in_sizes, int n_in,
                              void* d_out, int out_size) {
    const float* x       = (const float*)d_in[0];
    const float* noise   = (const float*)d_in[1];
    const float* w_route = (const float*)d_in[2];
    const float* b_route = (const float*)d_in[3];
    const float* w_noise = (const float*)d_in[4];
    const float* b_noise = (const float*)d_in[5];
    float* out = (float*)d_out;

    int n_tok = in_sizes[0] / N_EMBED;
    int write_idx = (out_size >= n_tok * NUM_EXPERTS + n_tok * 2) ? 1 : 0;

    cudaFuncSetAttribute(noisy_topk_router_kernel,
                         cudaFuncAttributeMaxDynamicSharedMemorySize, SMEM_TOTAL);

    int grid = (n_tok + TOK_PER_BLK - 1) / TOK_PER_BLK;   // 256
    noisy_topk_router_kernel<<<grid, THREADS, SMEM_TOTAL>>>(
        x, noise, w_route, b_route, w_noise, b_noise, out, n_tok, write_idx);
}